// round 15
// baseline (speedup 1.0000x reference)
#include <cuda_runtime.h>
#include <cuda_bf16.h>

// CenterLoss: loss = (1/(B*C)) * sum_i ||x_i - centers[labels_i]||^2
// B=4096, C=20000, D=128. Gather + reduce, single launch.
//
// FINAL KERNEL — converged best across 14 experimental rounds.
// Measured distribution for this source: kernel 5.31-5.57us, wall
// 6.66-6.88us (run-to-run noise +/-0.25us from NAT-clock DVFS).
//
// Structure: 512 blocks x 256 threads (8 warps), one row per warp.
//  - label load heads the dependent chain; x row load overlaps it;
//    center gather follows one memory trip later. All float4-vectorized.
//  - warp shuffle reduce -> 8 partials in shared -> lane<8 shuffle tree.
//  - ONE relaxed u64 atomicAdd per block: ticket in bits [63:50],
//    16.34 fixed-point partial in bits [49:0]. Integer adds are associative
//    -> bit-exact deterministic across graph replays (rel_err = 0).
//  - Block drawing the last ticket holds the grand total in-register,
//    writes the scaled output, and resets the accumulator with a plain
//    store (sole accessor; next replay ordered by the kernel boundary).
//
// Measured dead ends (do not revisit):
//  - __threadfence: gpu-scope => CCTL.IVALL L1 flush per block (+3us tail).
//  - acq_rel ticket + partials-array re-read: +2us.
//  - <=128 CTAs (any thread count): rollout imbalance, +0.3..0.8us.
//  - per-warp atomics (4096 same-address RMWs): last ticket waits behind
//    the serialized LTS queue, +2us.
//  - fire-and-forget RED + block-0 poll: neutral kernel, longer drain.
//  - separate reduce kernel: second launch costs ~3.5us GPU-side.
//
// Floor decomposition: fixed per-kernel cost ~3.5us (trivial-kernel
// measurement, R2) + intrinsic work ~1.5us + graph-replay gap ~1.3us
// = the observed wall. No kernel-side lever remains.

#define CL_BATCH 4096
#define CL_FEAT 128
#define CL_NCLASSES 20000
#define CL_WARPS 8
#define CL_THREADS (CL_WARPS * 32)                 // 256
#define CL_ROWS_PER_BLOCK CL_WARPS                 // one row per warp
#define CL_NBLOCKS (CL_BATCH / CL_ROWS_PER_BLOCK)  // 512

#define CL_TICKET_SHIFT 50
#define CL_SUM_MASK ((1ULL << CL_TICKET_SHIFT) - 1ULL)
#define CL_FIXED_SCALE 65536.0f  // 2^16 fractional bits

__device__ unsigned long long cl_g_acc = 0ULL;

__global__ void __launch_bounds__(CL_THREADS) cl_fused_kernel(
    const float* __restrict__ x,
    const int* __restrict__ labels,
    const float* __restrict__ centers,
    float* __restrict__ out)
{
    const int warp = threadIdx.x >> 5;
    const int lane = threadIdx.x & 31;
    const int row = blockIdx.x * CL_ROWS_PER_BLOCK + warp;

    // Head of the dependent chain: issue ASAP (broadcast load, 1 sector).
    const int lab = __ldg(&labels[row]);

    const float4* __restrict__ xr = reinterpret_cast<const float4*>(x + (size_t)row * CL_FEAT);
    float4 xv = xr[lane];  // independent of label, overlaps its latency

    const float4* __restrict__ cr = reinterpret_cast<const float4*>(centers + (size_t)lab * CL_FEAT);
    float4 cv = cr[lane];  // one dependent trip after label

    float dx = xv.x - cv.x;
    float dy = xv.y - cv.y;
    float dz = xv.z - cv.z;
    float dw = xv.w - cv.w;
    float s = dx * dx + dy * dy + dz * dz + dw * dw;

    // warp reduction
    #pragma unroll
    for (int o = 16; o > 0; o >>= 1)
        s += __shfl_xor_sync(0xffffffffu, s, o);

    __shared__ float sm[CL_WARPS];
    if (lane == 0) sm[warp] = s;
    __syncthreads();

    if (warp == 0) {
        // Shuffle-tree reduce of the 8 per-warp sums (lanes 0..7).
        float t = (lane < CL_WARPS) ? sm[lane] : 0.0f;
        #pragma unroll
        for (int o = 4; o > 0; o >>= 1)
            t += __shfl_xor_sync(0xffffffffu, t, o);

        if (lane == 0) {
            // Block partial ~ 1.1e3 -> fixed ~ 7.5e7; 512 blocks ~ 3.9e10 << 2^50.
            unsigned long long pkt =
                (1ULL << CL_TICKET_SHIFT) | __float2ull_rn(t * CL_FIXED_SCALE);

            unsigned long long old = atomicAdd(&cl_g_acc, pkt);

            if ((old >> CL_TICKET_SHIFT) == (unsigned long long)(CL_NBLOCKS - 1)) {
                unsigned long long total = (old + pkt) & CL_SUM_MASK;
                const float inv = 1.0f / ((float)CL_BATCH * (float)CL_NCLASSES);
                *out = (float)total * (1.0f / CL_FIXED_SCALE) * inv;
                // Sole accessor at this point; plain store resets for replay.
                cl_g_acc = 0ULL;
            }
        }
    }
}

extern "C" void kernel_launch(void* const* d_in, const int* in_sizes, int n_in,
                              void* d_out, int out_size)
{
    const float* x       = (const float*)d_in[0];
    const int*   labels  = (const int*)d_in[1];
    const float* centers = (const float*)d_in[2];
    float* out = (float*)d_out;

    cl_fused_kernel<<<CL_NBLOCKS, CL_THREADS>>>(x, labels, centers, out);
}

// round 16
// speedup vs baseline: 1.0386x; 1.0386x over previous
#include <cuda_runtime.h>
#include <cuda_bf16.h>

// CenterLoss: loss = (1/(B*C)) * sum_i ||x_i - centers[labels_i]||^2
// B=4096, C=20000, D=128. Gather + reduce, single launch.
//
// Shape probe: 2048 blocks x 64 threads (2 warps), one row per warp ->
// same 4096 warps as the converged best, but minimal per-CTA tail
// (1 barrier + single 2-wide shuffle + 1 atomic) and finest CLC
// load-balance granularity. Prior shape data: 128 CTAs worse, 512 ~ 1024
// CTAs best band; this tests the small-CTA endpoint.
//
// Cross-block reduction: ONE relaxed u64 atomicAdd per block carrying a
// ticket (bits [63:50]) + 16.34 fixed-point partial (bits [49:0]).
// Integer adds are associative -> bit-exact deterministic across graph
// replays (rel_err = 0). Block drawing the last ticket holds the grand
// total in-register, writes the scaled output, and resets the accumulator
// with a plain store (sole accessor; next replay ordered by the kernel
// boundary).
//
// Measured dead ends (do not revisit): __threadfence (+3us), acq_rel +
// partials re-read (+2us), <=128 CTAs (+0.3..0.8us), 4096 per-warp
// atomics (+2us), RED + block-0 poll (neutral/worse), split kernels
// (~3.5us second launch).

#define CL_BATCH 4096
#define CL_FEAT 128
#define CL_NCLASSES 20000
#define CL_WARPS 2
#define CL_THREADS (CL_WARPS * 32)                 // 64
#define CL_ROWS_PER_BLOCK CL_WARPS                 // one row per warp
#define CL_NBLOCKS (CL_BATCH / CL_ROWS_PER_BLOCK)  // 2048

#define CL_TICKET_SHIFT 50
#define CL_SUM_MASK ((1ULL << CL_TICKET_SHIFT) - 1ULL)
#define CL_FIXED_SCALE 65536.0f  // 2^16 fractional bits

__device__ unsigned long long cl_g_acc = 0ULL;

__global__ void __launch_bounds__(CL_THREADS) cl_fused_kernel(
    const float* __restrict__ x,
    const int* __restrict__ labels,
    const float* __restrict__ centers,
    float* __restrict__ out)
{
    const int warp = threadIdx.x >> 5;
    const int lane = threadIdx.x & 31;
    const int row = blockIdx.x * CL_ROWS_PER_BLOCK + warp;

    // Head of the dependent chain: issue ASAP (broadcast load, 1 sector).
    const int lab = __ldg(&labels[row]);

    const float4* __restrict__ xr = reinterpret_cast<const float4*>(x + (size_t)row * CL_FEAT);
    float4 xv = xr[lane];  // independent of label, overlaps its latency

    const float4* __restrict__ cr = reinterpret_cast<const float4*>(centers + (size_t)lab * CL_FEAT);
    float4 cv = cr[lane];  // one dependent trip after label

    float dx = xv.x - cv.x;
    float dy = xv.y - cv.y;
    float dz = xv.z - cv.z;
    float dw = xv.w - cv.w;
    float s = dx * dx + dy * dy + dz * dz + dw * dw;

    // warp reduction
    #pragma unroll
    for (int o = 16; o > 0; o >>= 1)
        s += __shfl_xor_sync(0xffffffffu, s, o);

    __shared__ float sm[CL_WARPS];
    if (lane == 0) sm[warp] = s;
    __syncthreads();

    if (warp == 0 && lane == 0) {
        // Two per-warp sums: trivial serial add (cheaper than a tree here).
        float t = sm[0] + sm[1];

        // Block partial ~ 280 -> fixed ~ 1.8e7; 2048 blocks ~ 3.9e10 << 2^50.
        unsigned long long pkt =
            (1ULL << CL_TICKET_SHIFT) | __float2ull_rn(t * CL_FIXED_SCALE);

        unsigned long long old = atomicAdd(&cl_g_acc, pkt);

        if ((old >> CL_TICKET_SHIFT) == (unsigned long long)(CL_NBLOCKS - 1)) {
            unsigned long long total = (old + pkt) & CL_SUM_MASK;
            const float inv = 1.0f / ((float)CL_BATCH * (float)CL_NCLASSES);
            *out = (float)total * (1.0f / CL_FIXED_SCALE) * inv;
            // Sole accessor at this point; plain store resets for replay.
            cl_g_acc = 0ULL;
        }
    }
}

extern "C" void kernel_launch(void* const* d_in, const int* in_sizes, int n_in,
                              void* d_out, int out_size)
{
    const float* x       = (const float*)d_in[0];
    const int*   labels  = (const int*)d_in[1];
    const float* centers = (const float*)d_in[2];
    float* out = (float*)d_out;

    cl_fused_kernel<<<CL_NBLOCKS, CL_THREADS>>>(x, labels, centers, out);
}